// round 2
// baseline (speedup 1.0000x reference)
#include <cuda_runtime.h>

// DynamicLIF persistent kernel for GB300 (sm_103a), round 2.
// (B,T,C,H,W) = (32,8,128,32,32). mem state in registers across all T steps.
// NEW vs R1: cp.async smem prefetch of x[t+1] issued BEFORE the per-batch
// barrier + tau-MLP (overlaps DRAM with sync latency), and a cheaper
// red.release / ld.acquire barrier (no threadfence drain).
// All tau-feeding arithmetic is bit-identical to R1 (rel_err was 0.0).

#define NB 32          // batch
#define NT 8           // time steps
#define NC 128         // channels
#define HW_ 1024       // H*W
#define CR 32          // C / red
#define THREADS 256
#define RPB 8          // channel rows per block
#define BPB 16         // blocks per batch (NC / RPB)
#define NBLOCKS (NB * BPB)   // 512

__device__ float    g_sums[NB * NC];
__device__ float    g_tau[NB];
__device__ unsigned g_count[NB];   // zero-init; returns to 0 each launch
__device__ unsigned g_gen[NB];     // monotonically increasing across replays

__device__ __forceinline__ unsigned ld_acquire(const unsigned* p) {
    unsigned v;
    asm volatile("ld.acquire.gpu.global.u32 %0, [%1];" : "=r"(v) : "l"(p));
    return v;
}
__device__ __forceinline__ void red_release_add(unsigned* p, unsigned v) {
    asm volatile("red.release.gpu.global.add.u32 [%0], %1;" :: "l"(p), "r"(v));
}

__global__ void __launch_bounds__(THREADS, 4)
lif_kernel(const float* __restrict__ x,
           const float* __restrict__ w1,
           const float* __restrict__ b1,
           const float* __restrict__ w2,
           const float* __restrict__ b2,
           float* __restrict__ out)
{
    __shared__ float4 s_buf[RPB * THREADS];   // 32 KB prefetch buffer
    __shared__ float  s_warp[8][RPB];
    __shared__ float  s_mean[NC];
    __shared__ float  s_tau;

    const int tid = threadIdx.x;
    const int blk = blockIdx.x;
    const int b   = blk >> 4;         // blk / BPB
    const int sub = blk & 15;         // blk % BPB
    const bool leader = (sub == 0);
    const int lane = tid & 31;
    const int warp = tid >> 5;

    // Generation base: stable at launch; correct across CUDA-graph replays.
    unsigned base_gen = 0;
    if (tid == 0) base_gen = *(volatile unsigned*)&g_gen[b];

    // This block owns channels c in [sub*RPB, sub*RPB+RPB) of batch b, all HW.
    const size_t row_base = ((size_t)b * NT * NC + (size_t)sub * RPB) * HW_;

    // Prologue: prefetch x[0] into smem.
    {
        const float4* xp = (const float4*)(x + row_base);
        #pragma unroll
        for (int i = 0; i < RPB; i++) {
            unsigned sa = (unsigned)__cvta_generic_to_shared(&s_buf[i * THREADS + tid]);
            asm volatile("cp.async.cg.shared.global [%0], [%1], 16;"
                         :: "r"(sa), "l"(xp + i * THREADS + tid));
        }
        asm volatile("cp.async.commit_group;");
    }

    float tau = 0.5f;                 // TAU0
    float4 mem[RPB];
    #pragma unroll
    for (int i = 0; i < RPB; i++) mem[i] = make_float4(0.f, 0.f, 0.f, 0.f);

    for (int t = 0; t < NT; t++) {
        float4* op = (float4*)(out + row_base + (size_t)t * NC * HW_);

        // ---- 0) wait for this step's prefetched x tile ----
        asm volatile("cp.async.wait_group 0;");
        __syncthreads();

        // ---- 1) mem = mem*tau + x (separate mul+add: matches JAX rounding),
        //         per-row partial sums for the mean. Bit-identical to R1. ----
        float part[RPB];
        #pragma unroll
        for (int i = 0; i < RPB; i++) {
            float4 xv = s_buf[i * THREADS + tid];
            float4 m = mem[i];
            m.x = __fadd_rn(__fmul_rn(m.x, tau), xv.x);
            m.y = __fadd_rn(__fmul_rn(m.y, tau), xv.y);
            m.z = __fadd_rn(__fmul_rn(m.z, tau), xv.z);
            m.w = __fadd_rn(__fmul_rn(m.w, tau), xv.w);
            mem[i] = m;
            part[i] = (m.x + m.y) + (m.z + m.w);
        }

        const bool need_tau = (t < NT - 1);

        // Warp-reduce each row's partial (identical order to R1).
        if (need_tau) {
            #pragma unroll
            for (int i = 0; i < RPB; i++) {
                float v = part[i];
                v += __shfl_xor_sync(0xffffffffu, v, 16);
                v += __shfl_xor_sync(0xffffffffu, v, 8);
                v += __shfl_xor_sync(0xffffffffu, v, 4);
                v += __shfl_xor_sync(0xffffffffu, v, 2);
                v += __shfl_xor_sync(0xffffffffu, v, 1);
                if (lane == 0) s_warp[warp][i] = v;
            }
        }
        __syncthreads();   // s_warp ready AND s_buf fully consumed

        // ---- 2) kick off prefetch of x[t+1] (overlaps barrier + MLP) ----
        if (t + 1 < NT) {
            const float4* xp = (const float4*)(x + row_base + (size_t)(t + 1) * NC * HW_);
            #pragma unroll
            for (int i = 0; i < RPB; i++) {
                unsigned sa = (unsigned)__cvta_generic_to_shared(&s_buf[i * THREADS + tid]);
                asm volatile("cp.async.cg.shared.global [%0], [%1], 16;"
                             :: "r"(sa), "l"(xp + i * THREADS + tid));
            }
            asm volatile("cp.async.commit_group;");
        }

        // ---- 3) publish this block's 8 channel sums + release-count ----
        if (need_tau && tid < RPB) {
            float s = 0.f;
            #pragma unroll
            for (int w = 0; w < 8; w++) s += s_warp[w][tid];
            __stcg(&g_sums[b * NC + sub * RPB + tid], s);
            red_release_add(&g_count[b], 1u);   // same-thread release orders the store
        }

        // ---- 4) spike + output + soft reset (overlaps barrier latency) ----
        #pragma unroll
        for (int i = 0; i < RPB; i++) {
            float4 m = mem[i];
            float4 sp;
            sp.x = (m.x > 1.0f) ? 1.0f : 0.0f;
            sp.y = (m.y > 1.0f) ? 1.0f : 0.0f;
            sp.z = (m.z > 1.0f) ? 1.0f : 0.0f;
            sp.w = (m.w > 1.0f) ? 1.0f : 0.0f;
            __stcs(op + i * THREADS + tid, sp);
            m.x = (m.x > 1.0f) ? 0.0f : m.x;
            m.y = (m.y > 1.0f) ? 0.0f : m.y;
            m.z = (m.z > 1.0f) ? 0.0f : m.z;
            m.w = (m.w > 1.0f) ? 0.0f : m.w;
            mem[i] = m;
        }

        if (!need_tau) break;

        // ---- 5) leader: wait for all 16 blocks' sums (128 releases), MLP ----
        if (leader) {
            if (tid == 0) {
                while (ld_acquire(&g_count[b]) != (unsigned)(BPB * RPB)) { }
                *(volatile unsigned*)&g_count[b] = 0;   // reset; ordered by gen release below
            }
            __syncthreads();
            if (tid < NC)
                s_mean[tid] = __ldcg(&g_sums[b * NC + tid]) * (1.0f / 1024.0f);
            __syncthreads();
            if (tid < CR) {
                float acc = b1[tid];
                #pragma unroll
                for (int c = 0; c < NC; c++)
                    acc = fmaf(w1[tid * NC + c], s_mean[c], acc);
                float e = fmaxf(acc, 0.0f);       // relu
                float p = e * w2[tid];
                p += __shfl_xor_sync(0xffffffffu, p, 16);
                p += __shfl_xor_sync(0xffffffffu, p, 8);
                p += __shfl_xor_sync(0xffffffffu, p, 4);
                p += __shfl_xor_sync(0xffffffffu, p, 2);
                p += __shfl_xor_sync(0xffffffffu, p, 1);
                if (tid == 0) {
                    float z = p + b2[0];
                    float tn = 1.0f / (1.0f + expf(-z));   // sigmoid
                    __stcg(&g_tau[b], tn);
                    red_release_add(&g_gen[b], 1u);         // releases tau + count reset
                }
            }
        }

        // ---- 6) all blocks: wait for new tau ----
        if (tid == 0) {
            unsigned tgt = base_gen + (unsigned)(t + 1);
            while (ld_acquire(&g_gen[b]) != tgt) { }
            s_tau = __ldcg(&g_tau[b]);
        }
        __syncthreads();
        tau = s_tau;
    }
}

extern "C" void kernel_launch(void* const* d_in, const int* in_sizes, int n_in,
                              void* d_out, int out_size)
{
    const float* x  = (const float*)d_in[0];
    const float* w1 = (const float*)d_in[1];
    const float* b1 = (const float*)d_in[2];
    const float* w2 = (const float*)d_in[3];
    const float* b2 = (const float*)d_in[4];
    float* out = (float*)d_out;

    lif_kernel<<<NBLOCKS, THREADS>>>(x, w1, b1, w2, b2, out);
}

// round 3
// speedup vs baseline: 1.3115x; 1.3115x over previous
#include <cuda_runtime.h>

// DynamicLIF persistent kernel for GB300 (sm_103a), round 3.
// Base = R1 (register-direct streaming, 78.5us, rel_err 0.0).
// Changes vs R1:
//  (1) Leaderless barrier: every block computes the tau-MLP redundantly from
//      g_sums (bit-identical math), killing the leader->gen->spinner hop.
//      Single monotonic per-batch counter, replay-safe (no reset).
//  (2) prefetch.global.L2 of x[t+1] issued before the spike/store/spin phase:
//      zero register cost, overlaps next step's DRAM pull with the barrier.

#define NB 32          // batch
#define NT 8           // time steps
#define NC 128         // channels
#define HW_ 1024       // H*W
#define CR 32          // C / red
#define THREADS 256
#define RPB 8          // channel rows per block
#define BPB 16         // blocks per batch (NC / RPB)
#define NBLOCKS (NB * BPB)   // 512

__device__ float    g_sums[NB * NC];
__device__ unsigned g_count[NB];   // monotonic across steps AND graph replays

__device__ __forceinline__ unsigned ld_acquire(const unsigned* p) {
    unsigned v;
    asm volatile("ld.acquire.gpu.global.u32 %0, [%1];" : "=r"(v) : "l"(p));
    return v;
}
__device__ __forceinline__ void red_release_add(unsigned* p, unsigned v) {
    asm volatile("red.release.gpu.global.add.u32 [%0], %1;" :: "l"(p), "r"(v));
}

__global__ void __launch_bounds__(THREADS, 4)
lif_kernel(const float* __restrict__ x,
           const float* __restrict__ w1,
           const float* __restrict__ b1,
           const float* __restrict__ w2,
           const float* __restrict__ b2,
           float* __restrict__ out)
{
    __shared__ float s_w1[CR * NC];   // 16 KB, every block caches w1 once
    __shared__ float s_warp[8][RPB];
    __shared__ float s_mean[NC];
    __shared__ float s_tau;

    const int tid = threadIdx.x;
    const int blk = blockIdx.x;
    const int b   = blk >> 4;         // blk / BPB
    const int sub = blk & 15;         // blk % BPB
    const int lane = tid & 31;
    const int warp = tid >> 5;

    // Every block caches w1 (used for the redundant per-block MLP).
    #pragma unroll
    for (int i = 0; i < (CR * NC) / THREADS; i++)
        s_w1[i * THREADS + tid] = w1[i * THREADS + tid];
    __syncthreads();

    // Monotonic barrier base: stable at launch (graph replays serialize).
    unsigned base_cnt = 0;
    if (tid == 0) base_cnt = *(volatile unsigned*)&g_count[b];

    float tau = 0.5f;                 // TAU0
    float4 mem[RPB];
    #pragma unroll
    for (int i = 0; i < RPB; i++) mem[i] = make_float4(0.f, 0.f, 0.f, 0.f);

    // This block owns channels c in [sub*RPB, sub*RPB+RPB) of batch b, all HW.
    const size_t row_base = ((size_t)b * NT * NC + (size_t)sub * RPB) * HW_;

    for (int t = 0; t < NT; t++) {
        const float4* xp = (const float4*)(x   + row_base + (size_t)t * NC * HW_);
        float4*       op = (float4*)      (out + row_base + (size_t)t * NC * HW_);

        // ---- 1) mem = mem*tau + x  (separate mul+add: matches JAX rounding),
        //         per-row partial sums. Bit-identical to R1. ----
        float part[RPB];
        #pragma unroll
        for (int i = 0; i < RPB; i++) {
            float4 xv = __ldcs(xp + i * THREADS + tid);
            float4 m = mem[i];
            m.x = __fadd_rn(__fmul_rn(m.x, tau), xv.x);
            m.y = __fadd_rn(__fmul_rn(m.y, tau), xv.y);
            m.z = __fadd_rn(__fmul_rn(m.z, tau), xv.z);
            m.w = __fadd_rn(__fmul_rn(m.w, tau), xv.w);
            mem[i] = m;
            part[i] = (m.x + m.y) + (m.z + m.w);
        }

        const bool need_tau = (t < NT - 1);   // last step: no MLP/barrier

        if (need_tau) {
            // Warp-reduce each row's partial (identical order to R1).
            #pragma unroll
            for (int i = 0; i < RPB; i++) {
                float v = part[i];
                v += __shfl_xor_sync(0xffffffffu, v, 16);
                v += __shfl_xor_sync(0xffffffffu, v, 8);
                v += __shfl_xor_sync(0xffffffffu, v, 4);
                v += __shfl_xor_sync(0xffffffffu, v, 2);
                v += __shfl_xor_sync(0xffffffffu, v, 1);
                if (lane == 0) s_warp[warp][i] = v;
            }
            __syncthreads();
            // Publish this block's 8 channel sums; release-count per storer.
            if (tid < RPB) {
                float s = 0.f;
                #pragma unroll
                for (int w = 0; w < 8; w++) s += s_warp[w][tid];
                __stcg(&g_sums[b * NC + sub * RPB + tid], s);
                red_release_add(&g_count[b], 1u);
            }
        }

        // ---- 2) L2 prefetch of x[t+1]: free overlap with stores + barrier ----
        if (t + 1 < NT) {
            const float* np = x + row_base + (size_t)(t + 1) * NC * HW_;
            #pragma unroll
            for (int i = 0; i < RPB; i++)
                asm volatile("prefetch.global.L2 [%0];"
                             :: "l"(np + (size_t)(i * THREADS + tid) * 4));
        }

        // ---- 3) spike + output + soft reset (overlaps barrier latency) ----
        #pragma unroll
        for (int i = 0; i < RPB; i++) {
            float4 m = mem[i];
            float4 sp;
            sp.x = (m.x > 1.0f) ? 1.0f : 0.0f;
            sp.y = (m.y > 1.0f) ? 1.0f : 0.0f;
            sp.z = (m.z > 1.0f) ? 1.0f : 0.0f;
            sp.w = (m.w > 1.0f) ? 1.0f : 0.0f;
            __stcs(op + i * THREADS + tid, sp);
            m.x = (m.x > 1.0f) ? 0.0f : m.x;
            m.y = (m.y > 1.0f) ? 0.0f : m.y;
            m.z = (m.z > 1.0f) ? 0.0f : m.z;
            m.w = (m.w > 1.0f) ? 0.0f : m.w;
            mem[i] = m;
        }

        if (!need_tau) break;

        // ---- 4) barrier: wait until all 16 blocks of this batch published ----
        if (tid == 0) {
            unsigned tgt = base_cnt + (unsigned)(BPB * RPB) * (unsigned)(t + 1);
            while ((int)(ld_acquire(&g_count[b]) - tgt) < 0) { }
        }
        __syncthreads();

        // ---- 5) redundant per-block MLP (bit-identical to R1's leader MLP) ----
        if (tid < NC)
            s_mean[tid] = __ldcg(&g_sums[b * NC + tid]) * (1.0f / 1024.0f);
        __syncthreads();
        if (tid < CR) {
            float acc = b1[tid];
            #pragma unroll
            for (int c = 0; c < NC; c++)
                acc = fmaf(s_w1[tid * NC + c], s_mean[c], acc);
            float e = fmaxf(acc, 0.0f);       // relu
            float p = e * w2[tid];
            p += __shfl_xor_sync(0xffffffffu, p, 16);
            p += __shfl_xor_sync(0xffffffffu, p, 8);
            p += __shfl_xor_sync(0xffffffffu, p, 4);
            p += __shfl_xor_sync(0xffffffffu, p, 2);
            p += __shfl_xor_sync(0xffffffffu, p, 1);
            if (tid == 0) {
                float z = p + b2[0];
                s_tau = 1.0f / (1.0f + expf(-z));   // sigmoid
            }
        }
        __syncthreads();
        tau = s_tau;
    }
}

extern "C" void kernel_launch(void* const* d_in, const int* in_sizes, int n_in,
                              void* d_out, int out_size)
{
    const float* x  = (const float*)d_in[0];
    const float* w1 = (const float*)d_in[1];
    const float* b1 = (const float*)d_in[2];
    const float* w2 = (const float*)d_in[3];
    const float* b2 = (const float*)d_in[4];
    float* out = (float*)d_out;

    lif_kernel<<<NBLOCKS, THREADS>>>(x, w1, b1, w2, b2, out);
}

// round 4
// speedup vs baseline: 1.3380x; 1.0202x over previous
#include <cuda_runtime.h>

// DynamicLIF persistent kernel for GB300 (sm_103a), round 4.
// Base = R1 streaming structure (78.5us, rel_err 0.0) + R3's proven
// redundant-MLP. NEW: per-batch rendezvous moves from L2 atomics to a
// CTA cluster: 8 blocks/batch, sums exchanged via st.shared::cluster into
// every peer's smem, completion via a cluster-scoped mbarrier. No global
// residency assumption (HW co-schedules each cluster), no L2 round-trips,
// no prefetch (R2/R3 showed prefetch poisons the LSU path).
// All tau-feeding arithmetic is bit-identical to R1 (rel_err was 0.0).

#define NB 32          // batch
#define NT 8           // time steps
#define NC 128         // channels
#define HW_ 1024       // H*W
#define CR 32          // C / red
#define THREADS 512
#define RPB 8          // float4 slices per thread
#define CPB 16         // channels per block
#define BPB 8          // blocks per batch (cluster size)
#define NBLOCKS (NB * BPB)   // 256
#define ARRIVALS (BPB * CPB) // 128 arrivals per mbarrier per step

__device__ __forceinline__ unsigned smem_u32(const void* p) {
    return (unsigned)__cvta_generic_to_shared(p);
}

__global__ void __launch_bounds__(THREADS, 2) __cluster_dims__(BPB, 1, 1)
lif_kernel(const float* __restrict__ x,
           const float* __restrict__ w1,
           const float* __restrict__ b1,
           const float* __restrict__ w2,
           const float* __restrict__ b2,
           float* __restrict__ out)
{
    __shared__ float s_w1[CR * NC];        // 16 KB
    __shared__ float s_warp[16][RPB];      // per-warp partials
    __shared__ float s_sums[2][NC];        // double-buffered batch sums (DSMEM target)
    __shared__ float s_mean[NC];
    __shared__ float s_tau;
    __shared__ __align__(8) unsigned long long s_mbar;

    const int tid  = threadIdx.x;
    const int lane = tid & 31;
    const int warp = tid >> 5;

    unsigned rank;
    asm("mov.u32 %0, %%cluster_ctarank;" : "=r"(rank));
    const int b   = blockIdx.x >> 3;     // batch
    const int sub = (int)rank;           // 0..7 within batch

    // Cache w1 in smem (for the redundant per-block MLP; bit-identical path).
    #pragma unroll
    for (int i = 0; i < (CR * NC) / THREADS; i++)
        s_w1[i * THREADS + tid] = w1[i * THREADS + tid];

    // Init cluster mbarrier, then cluster-sync so peers see it.
    const unsigned mbar_addr = smem_u32(&s_mbar);
    if (tid == 0)
        asm volatile("mbarrier.init.shared.b64 [%0], %1;"
                     :: "r"(mbar_addr), "r"(ARRIVALS) : "memory");
    __syncthreads();
    asm volatile("barrier.cluster.arrive.aligned;" ::: "memory");
    asm volatile("barrier.cluster.wait.aligned;" ::: "memory");

    float tau = 0.5f;                    // TAU0
    float4 mem[RPB];
    #pragma unroll
    for (int i = 0; i < RPB; i++) mem[i] = make_float4(0.f, 0.f, 0.f, 0.f);

    // This block owns channels [sub*CPB, sub*CPB+CPB) of batch b, all HW.
    const size_t row_base = ((size_t)b * NT * NC + (size_t)sub * CPB) * HW_;

    for (int t = 0; t < NT; t++) {
        const float4* xp = (const float4*)(x   + row_base + (size_t)t * NC * HW_);
        float4*       op = (float4*)      (out + row_base + (size_t)t * NC * HW_);

        // ---- 1) mem = mem*tau + x (separate mul+add: matches JAX rounding),
        //         per-slice partial sums. Bit-identical to R1. ----
        float part[RPB];
        #pragma unroll
        for (int i = 0; i < RPB; i++) {
            float4 xv = __ldcs(xp + i * THREADS + tid);
            float4 m = mem[i];
            m.x = __fadd_rn(__fmul_rn(m.x, tau), xv.x);
            m.y = __fadd_rn(__fmul_rn(m.y, tau), xv.y);
            m.z = __fadd_rn(__fmul_rn(m.z, tau), xv.z);
            m.w = __fadd_rn(__fmul_rn(m.w, tau), xv.w);
            mem[i] = m;
            part[i] = (m.x + m.y) + (m.z + m.w);
        }

        const bool need_tau = (t < NT - 1);

        if (need_tau) {
            // Warp-reduce each slice partial (identical shfl order to R1).
            #pragma unroll
            for (int i = 0; i < RPB; i++) {
                float v = part[i];
                v += __shfl_xor_sync(0xffffffffu, v, 16);
                v += __shfl_xor_sync(0xffffffffu, v, 8);
                v += __shfl_xor_sync(0xffffffffu, v, 4);
                v += __shfl_xor_sync(0xffffffffu, v, 2);
                v += __shfl_xor_sync(0xffffffffu, v, 1);
                if (lane == 0) s_warp[warp][i] = v;
            }
            __syncthreads();

            // Per-channel sums: slice i holds channels 2i (warps 0-7) and
            // 2i+1 (warps 8-15); warp-order summation == R1's order.
            if (tid < CPB) {
                const int lc = tid;                 // local channel 0..15
                const int i  = lc >> 1;
                const int wb = (lc & 1) * 8;
                float s = 0.f;
                #pragma unroll
                for (int w = 0; w < 8; w++) s += s_warp[wb + w][i];

                // Broadcast this channel's sum into every cluster CTA's smem,
                // then release-arrive on every CTA's mbarrier.
                const int buf = t & 1;
                const unsigned loc = smem_u32(&s_sums[buf][sub * CPB + lc]);
                #pragma unroll
                for (int r = 0; r < BPB; r++) {
                    unsigned rs, rb;
                    asm volatile("mapa.shared::cluster.u32 %0, %1, %2;"
                                 : "=r"(rs) : "r"(loc), "r"(r));
                    asm volatile("st.shared::cluster.f32 [%0], %1;"
                                 :: "r"(rs), "f"(s) : "memory");
                    asm volatile("mapa.shared::cluster.u32 %0, %1, %2;"
                                 : "=r"(rb) : "r"(mbar_addr), "r"(r));
                    asm volatile("mbarrier.arrive.release.cluster.shared::cluster.b64 _, [%0];"
                                 :: "r"(rb) : "memory");
                }
            }
        }

        // ---- 2) spike + output + soft reset (overlaps barrier latency) ----
        #pragma unroll
        for (int i = 0; i < RPB; i++) {
            float4 m = mem[i];
            float4 sp;
            sp.x = (m.x > 1.0f) ? 1.0f : 0.0f;
            sp.y = (m.y > 1.0f) ? 1.0f : 0.0f;
            sp.z = (m.z > 1.0f) ? 1.0f : 0.0f;
            sp.w = (m.w > 1.0f) ? 1.0f : 0.0f;
            __stcs(op + i * THREADS + tid, sp);
            m.x = (m.x > 1.0f) ? 0.0f : m.x;
            m.y = (m.y > 1.0f) ? 0.0f : m.y;
            m.z = (m.z > 1.0f) ? 0.0f : m.z;
            m.w = (m.w > 1.0f) ? 0.0f : m.w;
            mem[i] = m;
        }

        if (!need_tau) break;

        // ---- 3) wait for all 128 channel sums (cluster-scope acquire) ----
        {
            const unsigned parity = (unsigned)(t & 1);
            unsigned done;
            asm volatile(
                "{\n\t"
                ".reg .pred p;\n\t"
                "mbarrier.try_wait.parity.acquire.cluster.shared::cta.b64 p, [%1], %2;\n\t"
                "selp.b32 %0, 1, 0, p;\n\t"
                "}" : "=r"(done) : "r"(mbar_addr), "r"(parity) : "memory");
            if (!done) {
                asm volatile(
                    "{\n\t"
                    ".reg .pred P1;\n\t"
                    "LW%=:\n\t"
                    "mbarrier.try_wait.parity.acquire.cluster.shared::cta.b64 P1, [%0], %1, 0x989680;\n\t"
                    "@P1 bra.uni LD%=;\n\t"
                    "bra.uni LW%=;\n\t"
                    "LD%=:\n\t"
                    "}" :: "r"(mbar_addr), "r"(parity) : "memory");
            }
        }

        // ---- 4) redundant per-block MLP (bit-identical to R1/R3) ----
        if (tid < NC)
            s_mean[tid] = s_sums[t & 1][tid] * (1.0f / 1024.0f);
        __syncthreads();
        if (tid < CR) {
            float acc = b1[tid];
            #pragma unroll
            for (int c = 0; c < NC; c++)
                acc = fmaf(s_w1[tid * NC + c], s_mean[c], acc);
            float e = fmaxf(acc, 0.0f);        // relu
            float p = e * w2[tid];
            p += __shfl_xor_sync(0xffffffffu, p, 16);
            p += __shfl_xor_sync(0xffffffffu, p, 8);
            p += __shfl_xor_sync(0xffffffffu, p, 4);
            p += __shfl_xor_sync(0xffffffffu, p, 2);
            p += __shfl_xor_sync(0xffffffffu, p, 1);
            if (tid == 0) {
                float z = p + b2[0];
                s_tau = 1.0f / (1.0f + expf(-z));   // sigmoid
            }
        }
        __syncthreads();
        tau = s_tau;
    }

    // Quiesce the cluster before teardown; invalidate the mbarrier so the
    // next graph replay re-inits cleanly.
    asm volatile("barrier.cluster.arrive.aligned;" ::: "memory");
    asm volatile("barrier.cluster.wait.aligned;" ::: "memory");
    if (tid == 0)
        asm volatile("mbarrier.inval.shared.b64 [%0];" :: "r"(mbar_addr) : "memory");
}

extern "C" void kernel_launch(void* const* d_in, const int* in_sizes, int n_in,
                              void* d_out, int out_size)
{
    const float* x  = (const float*)d_in[0];
    const float* w1 = (const float*)d_in[1];
    const float* b1 = (const float*)d_in[2];
    const float* w2 = (const float*)d_in[3];
    const float* b2 = (const float*)d_in[4];
    float* out = (float*)d_out;

    lif_kernel<<<NBLOCKS, THREADS>>>(x, w1, b1, w2, b2, out);
}